// round 7
// baseline (speedup 1.0000x reference)
#include <cuda_runtime.h>

// LSTM_53815940218945: B=8192, T=256, I=1, H=50, O=1
// Block = 8 batch lanes, 200 threads (6.25 warps) -- ZERO dummy threads.
// Thread (q,s): q=j>>2 (cell 0..49), s=j&3 (k-split over KCH=13).
// Owns gate rows {q, 50+q, 100+q, 150+q} = (i,f,g,o) of cell q.
// Two lane-groups (batch lanes 0-3, 4-7) processed sequentially per step,
// reusing accumulator registers; group-B FMA overlaps group-A's MUFU chain.
// Reduce-scatter over the 4 split lanes (12 SHFL.32 per group, group masks).
// h double-buffered -> ONE barrier per step.

#define T_LEN  256
#define H      50
#define KCH    13     // k's per split (4*13 = 52 = H padded)
#define KP     52     // padded k rows in h planes
#define BT     8      // batch lanes per block

typedef unsigned long long u64;

__device__ __forceinline__ u64 pack2(float a, float b) {
    u64 r; asm("mov.b64 %0, {%1, %2};" : "=l"(r) : "f"(a), "f"(b)); return r;
}
__device__ __forceinline__ u64 fma2(u64 a, u64 b, u64 c) {
    u64 d; asm("fma.rn.f32x2 %0, %1, %2, %3;" : "=l"(d) : "l"(a), "l"(b), "l"(c));
    return d;
}
__device__ __forceinline__ u64 add2(u64 a, u64 b) {
    u64 d; asm("add.rn.f32x2 %0, %1, %2;" : "=l"(d) : "l"(a), "l"(b));
    return d;
}
__device__ __forceinline__ float lo_of(u64 v) {
    return __uint_as_float((unsigned)v);
}
__device__ __forceinline__ float hi_of(u64 v) {
    return __uint_as_float((unsigned)(v >> 32));
}
__device__ __forceinline__ float tanh_hw(float x) {
    float y; asm("tanh.approx.f32 %0, %1;" : "=f"(y) : "f"(x)); return y;
}
__device__ __forceinline__ float sigmoid_hw(float x) {
    return fmaf(0.5f, tanh_hw(0.5f * x), 0.5f);
}

__global__ void __launch_bounds__(200, 2) lstm_kernel(
    const float* __restrict__ x,      // [B, T, 1]
    const float* __restrict__ W_ih,   // [200, 1]
    const float* __restrict__ W_hh,   // [200, 50]
    const float* __restrict__ b_ih,   // [200]
    const float* __restrict__ b_hh,   // [200]
    const float* __restrict__ W_lin,  // [1, 50]
    const float* __restrict__ b_lin,  // [1]
    float* __restrict__ out)          // [B]
{
    __shared__ __align__(16) float x_s[T_LEN * BT];    // [t][lane]
    __shared__ __align__(16) float h2_s[2][KP * BT];   // [plane][k][lane]

    const int j = threadIdx.x;        // 0..199
    const int q = j >> 2;             // cell 0..49
    const int s = j & 3;              // k-split
    const int b0 = blockIdx.x * BT;
    const int k0 = s * KCH;

    // shfl group mask: the 4 lanes (split group) this thread belongs to
    const unsigned gmask = 0xFu << ((j & 31) & ~3);

    // Preload x tile: x_s[t][b] = x[(b0+b)*T + t]
    for (int i = j; i < T_LEN * BT; i += 200) {
        int b = i >> 8;
        int t = i & (T_LEN - 1);
        x_s[t * BT + b] = x[(b0 + b) * T_LEN + t];
    }
    // zero both h planes incl. pad rows 50,51 (never rewritten -> stay 0)
    for (int i = j; i < KP * BT; i += 200) {
        h2_s[0][i] = 0.0f;
        h2_s[1][i] = 0.0f;
    }

    // Weights: 4 gate rows x KCH ks, packed (w,w).
    u64 W2[4][KCH];
    float bias[4], wih[4];
    #pragma unroll
    for (int r = 0; r < 4; r++) {
        int row = r * H + q;  // PyTorch gate order i,f,g,o
        bias[r] = b_ih[row] + b_hh[row];
        wih[r]  = W_ih[row];
        #pragma unroll
        for (int i = 0; i < KCH; i++) {
            int k = k0 + i;
            float w = (k < H) ? W_hh[row * H + k] : 0.0f;
            W2[r][i] = pack2(w, w);
        }
    }
    float c_reg[2] = {0.0f, 0.0f};
    const bool lowhalf = (s < 2);
    const bool oddlane = (s & 1);

    __syncthreads();

    #pragma unroll 1
    for (int t = 0; t < T_LEN; t++) {
        const int ping = t & 1;
        const float* hplane = h2_s[ping];
        float* hnext = h2_s[ping ^ 1];

        #pragma unroll
        for (int g = 0; g < 2; g++) {
            // ---- gate partials for lanes [g*4, g*4+4): 13 LDS.128, 104 FFMA2
            u64 a[4][2];
            #pragma unroll
            for (int r = 0; r < 4; r++) { a[r][0] = 0ull; a[r][1] = 0ull; }
            #pragma unroll
            for (int i = 0; i < KCH; i++) {
                ulonglong2 hv = *reinterpret_cast<const ulonglong2*>(
                    &hplane[(k0 + i) * BT + g * 4]);
                #pragma unroll
                for (int r = 0; r < 4; r++) {
                    a[r][0] = fma2(W2[r][i], hv.x, a[r][0]);
                    a[r][1] = fma2(W2[r][i], hv.y, a[r][1]);
                }
            }

            // ---- reduce-scatter over the 4 split lanes (12 SHFL.32) ----
            u64 keep[4];
            #pragma unroll
            for (int r = 0; r < 4; r++) {
                u64 kv = lowhalf ? a[r][0] : a[r][1];
                u64 sv = lowhalf ? a[r][1] : a[r][0];
                u64 rv = __shfl_xor_sync(gmask, sv, 2);
                keep[r] = add2(kv, rv);
            }
            float g4[4];
            #pragma unroll
            for (int r = 0; r < 4; r++) {
                float mine  = oddlane ? hi_of(keep[r]) : lo_of(keep[r]);
                float sendf = oddlane ? lo_of(keep[r]) : hi_of(keep[r]);
                float rf = __shfl_xor_sync(gmask, sendf, 1);
                g4[r] = mine + rf;
            }

            // ---- pointwise update for (cell q, batch lane g*4+s) ----
            float xv = x_s[t * BT + g * 4 + s];
            float gi = fmaf(wih[0], xv, g4[0] + bias[0]);
            float gf = fmaf(wih[1], xv, g4[1] + bias[1]);
            float gg = fmaf(wih[2], xv, g4[2] + bias[2]);
            float go = fmaf(wih[3], xv, g4[3] + bias[3]);

            float i_ = sigmoid_hw(gi);
            float f_ = sigmoid_hw(gf);
            float g_ = tanh_hw(gg);
            float o_ = sigmoid_hw(go);
            c_reg[g] = fmaf(f_, c_reg[g], i_ * g_);
            float hn = o_ * tanh_hw(c_reg[g]);

            hnext[q * BT + g * 4 + s] = hn;
        }
        __syncthreads();
    }

    // Final h is in plane 0 (T_LEN even). out[b] = b_lin + sum_k h[k][b]*W_lin[k]
    if (j < BT) {
        const float* hf = h2_s[0];
        float sum = b_lin[0];
        #pragma unroll
        for (int k = 0; k < H; k++)
            sum = fmaf(hf[k * BT + j], W_lin[k], sum);
        out[b0 + j] = sum;
    }
}

extern "C" void kernel_launch(void* const* d_in, const int* in_sizes, int n_in,
                              void* d_out, int out_size) {
    const float* x     = (const float*)d_in[0];
    const float* W_ih  = (const float*)d_in[1];
    const float* W_hh  = (const float*)d_in[2];
    const float* b_ih  = (const float*)d_in[3];
    const float* b_hh  = (const float*)d_in[4];
    const float* W_lin = (const float*)d_in[5];
    const float* b_lin = (const float*)d_in[6];
    float* out = (float*)d_out;

    int B = in_sizes[0] / T_LEN;   // I = 1
    int blocks = B / BT;           // 1024 for B=8192

    lstm_kernel<<<blocks, 200>>>(x, W_ih, W_hh, b_ih, b_hh, W_lin, b_lin, out);
}